// round 1
// baseline (speedup 1.0000x reference)
#include <cuda_runtime.h>

#define Bb 2
#define Nn 128
#define Ll 128
#define Hh 8
#define Ee 64

// K/V/Q tile row pitch (pad 64 -> 68 keeps float4 alignment, breaks bank conflicts)
#define KP 68
// score/mask row pitch (pad 128 -> 132)
#define SP 132

// 64 MB scratch for V_t (temporal attention output), same layout as inputs [B,N,L,H,E]
__device__ float g_vt[(size_t)Bb * Nn * Ll * Hh * Ee];

// ---------------------------------------------------------------------------
// Kernel 1: temporal attention. One CTA per (b, n, h).
//   V_t[b,n,l,h,d] = softmax_s(scale * Q[b,n,l,h,:].K[b,n,s,h,:]) . V[b,n,s,h,d]
// ---------------------------------------------------------------------------
__global__ __launch_bounds__(128, 1)
void temporal_kernel(const float* __restrict__ q,
                     const float* __restrict__ k,
                     const float* __restrict__ v)
{
    extern __shared__ float smem[];
    float* Qs = smem;              // 128 x KP
    float* Ks = Qs + 128 * KP;     // 128 x KP
    float* Vs = Ks + 128 * KP;     // 128 x KP
    float* S  = Vs + 128 * KP;     // 128 x SP

    const int bid = blockIdx.x;
    const int h = bid % Hh;
    const int n = (bid / Hh) % Nn;
    const int b = bid / (Hh * Nn);
    const int t = threadIdx.x;

    // element (l, e) lives at base + l*(H*E) + e
    const int base = ((b * Nn + n) * Ll) * Hh * Ee + h * Ee;
    const int lstride = Hh * Ee;   // 512 floats

    // cooperative coalesced loads: 128 rows x 16 float4 each
    for (int idx = t; idx < 128 * 16; idx += 128) {
        const int row = idx >> 4;
        const int f   = idx & 15;
        const float4* gq = (const float4*)(q + base + row * lstride);
        const float4* gk = (const float4*)(k + base + row * lstride);
        const float4* gv = (const float4*)(v + base + row * lstride);
        *(float4*)(Qs + row * KP + f * 4) = gq[f];
        *(float4*)(Ks + row * KP + f * 4) = gk[f];
        *(float4*)(Vs + row * KP + f * 4) = gv[f];
    }
    __syncthreads();

    // this thread's q row -> registers
    float qreg[64];
#pragma unroll
    for (int f = 0; f < 16; f++) {
        float4 a = *(const float4*)(Qs + t * KP + f * 4);
        qreg[f * 4 + 0] = a.x; qreg[f * 4 + 1] = a.y;
        qreg[f * 4 + 2] = a.z; qreg[f * 4 + 3] = a.w;
    }

    // scores: S[t][s] = q_t . k_s   (Ks reads are warp-broadcast)
    for (int s = 0; s < 128; s++) {
        const float* kr = Ks + s * KP;
        float a0 = 0.f, a1 = 0.f, a2 = 0.f, a3 = 0.f;
#pragma unroll
        for (int e = 0; e < 64; e += 4) {
            float4 kv = *(const float4*)(kr + e);
            a0 = fmaf(qreg[e + 0], kv.x, a0);
            a1 = fmaf(qreg[e + 1], kv.y, a1);
            a2 = fmaf(qreg[e + 2], kv.z, a2);
            a3 = fmaf(qreg[e + 3], kv.w, a3);
        }
        S[t * SP + s] = (a0 + a1) + (a2 + a3);
    }

    // softmax over own row (thread-private, no sync needed)
    const float scale = 0.125f;  // 1/sqrt(64)
    float m = -1e30f;
    for (int s = 0; s < 128; s++) m = fmaxf(m, S[t * SP + s]);
    float ssum = 0.f;
    for (int s = 0; s < 128; s++) {
        float p = __expf(scale * (S[t * SP + s] - m));
        ssum += p;
        S[t * SP + s] = p;
    }
    const float inv = 1.0f / ssum;

    // PV: acc[d] = sum_s p[s] * V[s][d]
    float acc[64];
#pragma unroll
    for (int d = 0; d < 64; d++) acc[d] = 0.f;
    for (int s = 0; s < 128; s++) {
        const float p = S[t * SP + s];
        const float* vr = Vs + s * KP;
#pragma unroll
        for (int d = 0; d < 64; d += 4) {
            float4 vv = *(const float4*)(vr + d);
            acc[d + 0] = fmaf(p, vv.x, acc[d + 0]);
            acc[d + 1] = fmaf(p, vv.y, acc[d + 1]);
            acc[d + 2] = fmaf(p, vv.z, acc[d + 2]);
            acc[d + 3] = fmaf(p, vv.w, acc[d + 3]);
        }
    }

    float* o = g_vt + base + t * lstride;
#pragma unroll
    for (int d = 0; d < 64; d += 4) {
        float4 w = make_float4(acc[d] * inv, acc[d + 1] * inv,
                               acc[d + 2] * inv, acc[d + 3] * inv);
        *(float4*)(o + d) = w;
    }
}

// ---------------------------------------------------------------------------
// Kernel 2: spatial attention. One CTA per (b, l, h).
//   out[b,n,l,h,d] = softmax_m(scale * mask[b,n,m] * Q[b,n,l,h,:].K[b,m,l,h,:])
//                    . V_t[b,m,l,h,d]
// ---------------------------------------------------------------------------
__global__ __launch_bounds__(128, 1)
void spatial_kernel(const float* __restrict__ q,
                    const float* __restrict__ k,
                    const float* __restrict__ mask,
                    float* __restrict__ out)
{
    extern __shared__ float smem[];
    float* Ks = smem;              // 128 x KP
    float* Vs = Ks + 128 * KP;     // 128 x KP   (V_t tile)
    float* S  = Vs + 128 * KP;     // 128 x SP
    float* Ms = S  + 128 * SP;     // 128 x SP   (mask tile)

    const int bid = blockIdx.x;
    const int h = bid % Hh;
    const int l = (bid / Hh) % Ll;
    const int b = bid / (Hh * Ll);
    const int t = threadIdx.x;

    // element (n, e) lives at base + n*(L*H*E) + e
    const int base = (b * Nn * Ll + l) * Hh * Ee + h * Ee;
    const int nstride = Ll * Hh * Ee;  // 65536 floats

    // K and V_t tiles (coalesced 256B rows)
    for (int idx = t; idx < 128 * 16; idx += 128) {
        const int row = idx >> 4;
        const int f   = idx & 15;
        const float4* gk = (const float4*)(k    + base + row * nstride);
        const float4* gv = (const float4*)(g_vt + base + row * nstride);
        *(float4*)(Ks + row * KP + f * 4) = gk[f];
        *(float4*)(Vs + row * KP + f * 4) = gv[f];
    }
    // mask tile: mask[b][n][m], 128x128 floats = 4096 float4
    {
        const float4* gm = (const float4*)(mask + b * Nn * Nn);
        for (int idx = t; idx < 128 * 32; idx += 128) {
            const int row = idx >> 5;
            const int f   = idx & 31;
            *(float4*)(Ms + row * SP + f * 4) = gm[row * 32 + f];
        }
    }

    // this thread's q row, straight from global (256B contiguous per thread)
    float qreg[64];
    {
        const float4* gq = (const float4*)(q + base + t * nstride);
#pragma unroll
        for (int f = 0; f < 16; f++) {
            float4 a = gq[f];
            qreg[f * 4 + 0] = a.x; qreg[f * 4 + 1] = a.y;
            qreg[f * 4 + 2] = a.z; qreg[f * 4 + 3] = a.w;
        }
    }
    __syncthreads();

    // masked scores: S[t][m] = (q_t . k_m) * mask[t][m]
    for (int s = 0; s < 128; s++) {
        const float* kr = Ks + s * KP;
        float a0 = 0.f, a1 = 0.f, a2 = 0.f, a3 = 0.f;
#pragma unroll
        for (int e = 0; e < 64; e += 4) {
            float4 kv = *(const float4*)(kr + e);
            a0 = fmaf(qreg[e + 0], kv.x, a0);
            a1 = fmaf(qreg[e + 1], kv.y, a1);
            a2 = fmaf(qreg[e + 2], kv.z, a2);
            a3 = fmaf(qreg[e + 3], kv.w, a3);
        }
        S[t * SP + s] = ((a0 + a1) + (a2 + a3)) * Ms[t * SP + s];
    }

    // softmax over own row
    const float scale = 0.125f;
    float m = -1e30f;
    for (int s = 0; s < 128; s++) m = fmaxf(m, S[t * SP + s]);
    float ssum = 0.f;
    for (int s = 0; s < 128; s++) {
        float p = __expf(scale * (S[t * SP + s] - m));
        ssum += p;
        S[t * SP + s] = p;
    }
    const float inv = 1.0f / ssum;

    // out row = sum_m p[m] * V_t[m][:]
    float acc[64];
#pragma unroll
    for (int d = 0; d < 64; d++) acc[d] = 0.f;
    for (int s = 0; s < 128; s++) {
        const float p = S[t * SP + s];
        const float* vr = Vs + s * KP;
#pragma unroll
        for (int d = 0; d < 64; d += 4) {
            float4 vv = *(const float4*)(vr + d);
            acc[d + 0] = fmaf(p, vv.x, acc[d + 0]);
            acc[d + 1] = fmaf(p, vv.y, acc[d + 1]);
            acc[d + 2] = fmaf(p, vv.z, acc[d + 2]);
            acc[d + 3] = fmaf(p, vv.w, acc[d + 3]);
        }
    }

    float* o = out + base + t * nstride;
#pragma unroll
    for (int d = 0; d < 64; d += 4) {
        float4 w = make_float4(acc[d] * inv, acc[d + 1] * inv,
                               acc[d + 2] * inv, acc[d + 3] * inv);
        *(float4*)(o + d) = w;
    }
}

// ---------------------------------------------------------------------------
extern "C" void kernel_launch(void* const* d_in, const int* in_sizes, int n_in,
                              void* d_out, int out_size)
{
    const float* q    = (const float*)d_in[0];
    const float* k    = (const float*)d_in[1];
    const float* v    = (const float*)d_in[2];
    const float* mask = (const float*)d_in[3];
    float* out = (float*)d_out;

    const size_t smem1 = (size_t)(3 * 128 * KP + 128 * SP) * sizeof(float); // 172 KB
    const size_t smem2 = (size_t)(2 * 128 * KP + 2 * 128 * SP) * sizeof(float); // 205 KB

    cudaFuncSetAttribute(temporal_kernel,
                         cudaFuncAttributeMaxDynamicSharedMemorySize, (int)smem1);
    cudaFuncSetAttribute(spatial_kernel,
                         cudaFuncAttributeMaxDynamicSharedMemorySize, (int)smem2);

    temporal_kernel<<<Bb * Nn * Hh, 128, smem1>>>(q, k, v);
    spatial_kernel<<<Bb * Ll * Hh, 128, smem2>>>(q, k, mask, out);
}

// round 3
// speedup vs baseline: 3.2710x; 3.2710x over previous
#include <cuda_runtime.h>
#include <cuda_bf16.h>
#include <cstdint>

#define Bb 2
#define Nn 128
#define Ll 128
#define Hh 8
#define Ee 64

// ---- smem layout (bytes). Q/K/V bf16 tiles: 128 rows x 64 cols, pitch 144B
//      (144B = 36 banks ≡ 4 mod 32 -> conflict-free ldmatrix, no swizzle).
#define QP 144
#define PP 272          // P tiles: 128 x 128 bf16, pitch 272B (68 banks ≡ 4 mod 32)
#define SQ_H 0
#define SQ_L 18432
#define SK_H 36864
#define SK_L 55296
#define SV_H 73728
#define SV_L 92160
#define SM_TOTAL 110592
// P region aliases the dead Q/K region after softmax (needs 2x34816 = 69632 <= 73728)
#define SP_H 0
#define SP_L 34816

__device__ float g_vt[(size_t)Bb * Nn * Ll * Hh * Ee];   // temporal-stage output

// ---------------- helpers ----------------
__device__ __forceinline__ uint32_t smem_u32(const void* p) {
    uint32_t a;
    asm("{ .reg .u64 t; cvta.to.shared.u64 t, %1; cvt.u32.u64 %0, t; }"
        : "=r"(a) : "l"(p));
    return a;
}
__device__ __forceinline__ void ldsm4(uint32_t* r, uint32_t a) {
    asm volatile("ldmatrix.sync.aligned.m8n8.x4.shared.b16 {%0,%1,%2,%3}, [%4];"
                 : "=r"(r[0]), "=r"(r[1]), "=r"(r[2]), "=r"(r[3]) : "r"(a));
}
__device__ __forceinline__ void ldsm4t(uint32_t* r, uint32_t a) {
    asm volatile("ldmatrix.sync.aligned.m8n8.x4.trans.shared.b16 {%0,%1,%2,%3}, [%4];"
                 : "=r"(r[0]), "=r"(r[1]), "=r"(r[2]), "=r"(r[3]) : "r"(a));
}
__device__ __forceinline__ void mma16816(float* c, const uint32_t* a, const uint32_t* b) {
    asm volatile(
        "mma.sync.aligned.m16n8k16.row.col.f32.bf16.bf16.f32 "
        "{%0,%1,%2,%3}, {%4,%5,%6,%7}, {%8,%9}, {%0,%1,%2,%3};"
        : "+f"(c[0]), "+f"(c[1]), "+f"(c[2]), "+f"(c[3])
        : "r"(a[0]), "r"(a[1]), "r"(a[2]), "r"(a[3]), "r"(b[0]), "r"(b[1]));
}
__device__ __forceinline__ uint32_t packbf(float x, float y) {
    __nv_bfloat162 v = __floats2bfloat162_rn(x, y);
    return *(uint32_t*)&v;
}
// hi/lo split: x ~= hi + lo with hi,lo bf16
__device__ __forceinline__ void split2(float x, float y, uint32_t& hi, uint32_t& lo) {
    __nv_bfloat16 hx = __float2bfloat16(x), hy = __float2bfloat16(y);
    __nv_bfloat16 lx = __float2bfloat16(x - __bfloat162float(hx));
    __nv_bfloat16 ly = __float2bfloat16(y - __bfloat162float(hy));
    uint16_t a = *(uint16_t*)&hx, b2 = *(uint16_t*)&hy;
    uint16_t c = *(uint16_t*)&lx, d = *(uint16_t*)&ly;
    hi = (uint32_t)a | ((uint32_t)b2 << 16);
    lo = (uint32_t)c | ((uint32_t)d << 16);
}

// ---------------------------------------------------------------------------
template <bool SPATIAL>
__global__ __launch_bounds__(256, 2)
void attn_mma_kernel(const float* __restrict__ q, const float* __restrict__ k,
                     const float* __restrict__ vsrc, const float* __restrict__ mask,
                     float* __restrict__ out)
{
    extern __shared__ char sm[];
    const uint32_t sb = smem_u32(sm);
    const int t = threadIdx.x, lane = t & 31, wid = t >> 5;

    const int pid = blockIdx.x;
    const int h = pid & 7;
    const int rl = (pid >> 3) & 127;            // n (temporal) or l (spatial)
    const int b = pid >> 10;
    int base, rstride;
    if (SPATIAL) { base = (b * Nn * Ll + rl) * (Hh * Ee) + h * Ee; rstride = Ll * Hh * Ee; }
    else         { base = ((b * Nn + rl) * Ll) * (Hh * Ee) + h * Ee; rstride = Hh * Ee; }

    const float* __restrict__ vp = SPATIAL ? (const float*)g_vt : vsrc;
    float* __restrict__ dst = SPATIAL ? out : (float*)g_vt;

    // ---- load + bf16 hi/lo convert: Q, K, V (all row-major seq x 64) ----
#pragma unroll
    for (int i = 0; i < 16; i++) {
        const int idx = i * 256 + t;
        const int row = idx >> 5, e2 = idx & 31;           // e2: float2 index
        const int go = base + row * rstride + e2 * 2;
        const float2 qv = *(const float2*)(q + go);
        const float2 kv = *(const float2*)(k + go);
        const float2 vv = *(const float2*)(vp + go);
        const uint32_t off = (uint32_t)(row * QP + e2 * 4);
        uint32_t hi, lo;
        split2(qv.x, qv.y, hi, lo);
        *(uint32_t*)(sm + SQ_H + off) = hi; *(uint32_t*)(sm + SQ_L + off) = lo;
        split2(kv.x, kv.y, hi, lo);
        *(uint32_t*)(sm + SK_H + off) = hi; *(uint32_t*)(sm + SK_L + off) = lo;
        split2(vv.x, vv.y, hi, lo);
        *(uint32_t*)(sm + SV_H + off) = hi; *(uint32_t*)(sm + SV_L + off) = lo;
    }
    __syncthreads();

    // ---- QK^T: warp owns rows r0..r0+15; full N=128 in C frags ----
    const int r0 = wid * 16;
    float c[16][4];
#pragma unroll
    for (int nt = 0; nt < 16; nt++)
#pragma unroll
        for (int j = 0; j < 4; j++) c[nt][j] = 0.f;

#pragma unroll
    for (int term = 0; term < 3; term++) {
        const uint32_t Ab = sb + (term < 2 ? SQ_H : SQ_L);
        const uint32_t Bb2 = sb + (term == 1 ? SK_L : SK_H);
        uint32_t a[4][4];
        const uint32_t arow = Ab + (uint32_t)((r0 + (lane & 15)) * QP + (lane >> 4) * 16);
#pragma unroll
        for (int ks = 0; ks < 4; ks++) ldsm4(a[ks], arow + ks * 32);
#pragma unroll
        for (int nt = 0; nt < 16; nt++) {
            const uint32_t brow = Bb2 + (uint32_t)((nt * 8 + (lane & 7)) * QP + ((lane >> 3) & 3) * 16);
            uint32_t b0[4], b1[4];
            ldsm4(b0, brow);          // k 0..31  (2 ksteps)
            ldsm4(b1, brow + 64);     // k 32..63
            mma16816(c[nt], a[0], b0);
            mma16816(c[nt], a[1], b0 + 2);
            mma16816(c[nt], a[2], b1);
            mma16816(c[nt], a[3], b1 + 2);
        }
    }
    __syncthreads();   // everyone done reading Q/K before P overwrites them

    // ---- mask (spatial) + softmax over each row (regs + quad shuffles) ----
    const int row_lo = r0 + (lane >> 2);
    const int row_hi = row_lo + 8;
    if (SPATIAL) {
        const float* mrow_lo = mask + ((size_t)b * Nn + row_lo) * Nn;
        const float* mrow_hi = mask + ((size_t)b * Nn + row_hi) * Nn;
#pragma unroll
        for (int nt = 0; nt < 16; nt++) {
            const int col = nt * 8 + (lane & 3) * 2;
            const float2 ml = *(const float2*)(mrow_lo + col);
            const float2 mh = *(const float2*)(mrow_hi + col);
            c[nt][0] *= ml.x; c[nt][1] *= ml.y;
            c[nt][2] *= mh.x; c[nt][3] *= mh.y;
        }
    }
    float mlo = -1e30f, mhi = -1e30f;
#pragma unroll
    for (int nt = 0; nt < 16; nt++) {
        mlo = fmaxf(mlo, fmaxf(c[nt][0], c[nt][1]));
        mhi = fmaxf(mhi, fmaxf(c[nt][2], c[nt][3]));
    }
    mlo = fmaxf(mlo, __shfl_xor_sync(0xFFFFFFFF, mlo, 1));
    mlo = fmaxf(mlo, __shfl_xor_sync(0xFFFFFFFF, mlo, 2));
    mhi = fmaxf(mhi, __shfl_xor_sync(0xFFFFFFFF, mhi, 1));
    mhi = fmaxf(mhi, __shfl_xor_sync(0xFFFFFFFF, mhi, 2));
    float slo = 0.f, shi = 0.f;
#pragma unroll
    for (int nt = 0; nt < 16; nt++) {
        c[nt][0] = __expf(0.125f * (c[nt][0] - mlo));
        c[nt][1] = __expf(0.125f * (c[nt][1] - mlo));
        c[nt][2] = __expf(0.125f * (c[nt][2] - mhi));
        c[nt][3] = __expf(0.125f * (c[nt][3] - mhi));
        slo += c[nt][0] + c[nt][1];
        shi += c[nt][2] + c[nt][3];
    }
    slo += __shfl_xor_sync(0xFFFFFFFF, slo, 1);
    slo += __shfl_xor_sync(0xFFFFFFFF, slo, 2);
    shi += __shfl_xor_sync(0xFFFFFFFF, shi, 1);
    shi += __shfl_xor_sync(0xFFFFFFFF, shi, 2);
    const float invlo = 1.0f / slo, invhi = 1.0f / shi;

    // ---- write P hi/lo into smem (row-major, pitch PP) ----
#pragma unroll
    for (int nt = 0; nt < 16; nt++) {
        const uint32_t colb = (uint32_t)((nt * 8 + (lane & 3) * 2) * 2);
        uint32_t hi, lo;
        split2(c[nt][0], c[nt][1], hi, lo);
        *(uint32_t*)(sm + SP_H + row_lo * PP + colb) = hi;
        *(uint32_t*)(sm + SP_L + row_lo * PP + colb) = lo;
        split2(c[nt][2], c[nt][3], hi, lo);
        *(uint32_t*)(sm + SP_H + row_hi * PP + colb) = hi;
        *(uint32_t*)(sm + SP_L + row_hi * PP + colb) = lo;
    }
    __syncthreads();

    // ---- PV: O(16x64 per warp) = P(16x128) * V(128x64), 3 split terms ----
    float o[8][4];
#pragma unroll
    for (int nt = 0; nt < 8; nt++)
#pragma unroll
        for (int j = 0; j < 4; j++) o[nt][j] = 0.f;

#pragma unroll
    for (int term = 0; term < 3; term++) {
        const uint32_t Ab = sb + (term < 2 ? SP_H : SP_L);
        const uint32_t Bb2 = sb + (term == 1 ? SV_L : SV_H);
        const uint32_t arow = Ab + (uint32_t)((r0 + (lane & 15)) * PP + (lane >> 4) * 16);
        const uint32_t brow0 = Bb2 + (uint32_t)(((lane & 7) + ((lane >> 3) & 1) * 8) * QP + ((lane >> 4) & 1) * 16);
#pragma unroll
        for (int ks = 0; ks < 8; ks++) {
            uint32_t a[4];
            ldsm4(a, arow + ks * 32);
            const uint32_t bk = brow0 + (uint32_t)(ks * 16 * QP);
#pragma unroll
            for (int p = 0; p < 4; p++) {
                uint32_t bb[4];
                ldsm4t(bb, bk + p * 32);
                mma16816(o[p * 2], a, bb);
                mma16816(o[p * 2 + 1], a, bb + 2);
            }
        }
    }

    // ---- epilogue: divide by softmax sum, store ----
    float* orow_lo = dst + base + row_lo * rstride;
    float* orow_hi = dst + base + row_hi * rstride;
#pragma unroll
    for (int nt = 0; nt < 8; nt++) {
        const int col = nt * 8 + (lane & 3) * 2;
        float2 w0 = make_float2(o[nt][0] * invlo, o[nt][1] * invlo);
        float2 w1 = make_float2(o[nt][2] * invhi, o[nt][3] * invhi);
        *(float2*)(orow_lo + col) = w0;
        *(float2*)(orow_hi + col) = w1;
    }
}

// ---------------------------------------------------------------------------
extern "C" void kernel_launch(void* const* d_in, const int* in_sizes, int n_in,
                              void* d_out, int out_size)
{
    const float* q    = (const float*)d_in[0];
    const float* k    = (const float*)d_in[1];
    const float* v    = (const float*)d_in[2];
    const float* mask = (const float*)d_in[3];
    float* out = (float*)d_out;

    cudaFuncSetAttribute(attn_mma_kernel<false>,
                         cudaFuncAttributeMaxDynamicSharedMemorySize, SM_TOTAL);
    cudaFuncSetAttribute(attn_mma_kernel<true>,
                         cudaFuncAttributeMaxDynamicSharedMemorySize, SM_TOTAL);

    attn_mma_kernel<false><<<Bb * Nn * Hh, 256, SM_TOTAL>>>(q, k, v, nullptr, out);
    attn_mma_kernel<true><<<Bb * Ll * Hh, 256, SM_TOTAL>>>(q, k, v, mask, out);
}

// round 4
// speedup vs baseline: 5.4959x; 1.6802x over previous
#include <cuda_runtime.h>
#include <cuda_bf16.h>
#include <cstdint>

#define Bb 2
#define Nn 128
#define Ll 128
#define Hh 8
#define Ee 64

// smem: Q/K bf16 hi/lo tiles, 128 rows x 64 cols, pitch 144B (36 banks ≡ 4 mod 32
// -> conflict-free ldmatrix). V hi/lo overwrites the Q region after MMA1.
#define QP 144
#define SQ_H 0
#define SQ_L 18432
#define SK_H 36864
#define SK_L 55296
#define SM_TOTAL 73728
#define SV_H 0
#define SV_L 18432

// V_t stored packed: per element u32 = bf16_hi | bf16_lo<<16
__device__ uint32_t g_vt[(size_t)Bb * Nn * Ll * Hh * Ee];

// ---------------- helpers ----------------
__device__ __forceinline__ uint32_t smem_u32(const void* p) {
    uint32_t a;
    asm("{ .reg .u64 t; cvta.to.shared.u64 t, %1; cvt.u32.u64 %0, t; }"
        : "=r"(a) : "l"(p));
    return a;
}
__device__ __forceinline__ void ldsm4(uint32_t* r, uint32_t a) {
    asm volatile("ldmatrix.sync.aligned.m8n8.x4.shared.b16 {%0,%1,%2,%3}, [%4];"
                 : "=r"(r[0]), "=r"(r[1]), "=r"(r[2]), "=r"(r[3]) : "r"(a));
}
__device__ __forceinline__ void ldsm4t(uint32_t* r, uint32_t a) {
    asm volatile("ldmatrix.sync.aligned.m8n8.x4.trans.shared.b16 {%0,%1,%2,%3}, [%4];"
                 : "=r"(r[0]), "=r"(r[1]), "=r"(r[2]), "=r"(r[3]) : "r"(a));
}
__device__ __forceinline__ void mma16816(float* c, const uint32_t* a, const uint32_t* b) {
    asm volatile(
        "mma.sync.aligned.m16n8k16.row.col.f32.bf16.bf16.f32 "
        "{%0,%1,%2,%3}, {%4,%5,%6,%7}, {%8,%9}, {%0,%1,%2,%3};"
        : "+f"(c[0]), "+f"(c[1]), "+f"(c[2]), "+f"(c[3])
        : "r"(a[0]), "r"(a[1]), "r"(a[2]), "r"(a[3]), "r"(b[0]), "r"(b[1]));
}
// bf16x2 pack: x->low, y->high
__device__ __forceinline__ uint32_t cvt_bf16x2(float y, float x) {
    uint32_t r;
    asm("cvt.rn.bf16x2.f32 %0, %1, %2;" : "=r"(r) : "f"(y), "f"(x));
    return r;
}
// hi = truncated-bf16 pair (PRMT), lo = rn-bf16 of exact residuals
__device__ __forceinline__ void split_pair(float x, float y, uint32_t& hi, uint32_t& lo) {
    const uint32_t u0 = __float_as_uint(x), u1 = __float_as_uint(y);
    hi = __byte_perm(u0, u1, 0x7632);
    const float l0 = x - __uint_as_float(u0 & 0xFFFF0000u);
    const float l1 = y - __uint_as_float(u1 & 0xFFFF0000u);
    lo = cvt_bf16x2(l1, l0);
}

// ---------------------------------------------------------------------------
template <bool SPATIAL>
__global__ __launch_bounds__(256, 2)
void attn_mma_kernel(const float* __restrict__ q, const float* __restrict__ k,
                     const float* __restrict__ v32, const uint32_t* __restrict__ vpk,
                     const float* __restrict__ mask,
                     uint32_t* __restrict__ dst_pk, float* __restrict__ dst_f)
{
    extern __shared__ char sm[];
    const uint32_t sb = smem_u32(sm);
    const int t = threadIdx.x, lane = t & 31, wid = t >> 5;

    const int pid = blockIdx.x;
    const int h = pid & 7;
    const int rl = (pid >> 3) & 127;
    const int b = pid >> 10;
    int base, rstride;
    if (SPATIAL) { base = (b * Nn * Ll + rl) * (Hh * Ee) + h * Ee; rstride = Ll * Hh * Ee; }
    else         { base = ((b * Nn + rl) * Ll) * (Hh * Ee) + h * Ee; rstride = Hh * Ee; }

    // Q pre-scaled by softmax scale * log2(e): exp(0.125 s) == exp2(QS s)
    const float QS = 0.125f * 1.44269504088896f;

    // ---- load + convert Q (scaled), K ----
#pragma unroll
    for (int i = 0; i < 16; i++) {
        const int idx = i * 256 + t;
        const int row = idx >> 5, e2 = idx & 31;
        const int go = base + row * rstride + e2 * 2;
        float2 qv = *(const float2*)(q + go);
        const float2 kv = *(const float2*)(k + go);
        qv.x *= QS; qv.y *= QS;
        const uint32_t off = (uint32_t)(row * QP + e2 * 4);
        uint32_t hi, lo;
        split_pair(qv.x, qv.y, hi, lo);
        *(uint32_t*)(sm + SQ_H + off) = hi; *(uint32_t*)(sm + SQ_L + off) = lo;
        split_pair(kv.x, kv.y, hi, lo);
        *(uint32_t*)(sm + SK_H + off) = hi; *(uint32_t*)(sm + SK_L + off) = lo;
    }
    __syncthreads();

    // ---- MMA1: S = Qh*Kh + Qh*Kl + Ql*Kh (3-term bf16 split, fp32 accum) ----
    const int r0 = wid * 16;
    float c[16][4];
#pragma unroll
    for (int nt = 0; nt < 16; nt++)
#pragma unroll
        for (int j = 0; j < 4; j++) c[nt][j] = 0.f;

#pragma unroll
    for (int term = 0; term < 3; term++) {
        const uint32_t Ab = sb + (term < 2 ? SQ_H : SQ_L);
        const uint32_t Bbs = sb + (term == 1 ? SK_L : SK_H);
        uint32_t a[4][4];
        const uint32_t arow = Ab + (uint32_t)((r0 + (lane & 15)) * QP + (lane >> 4) * 16);
#pragma unroll
        for (int ks = 0; ks < 4; ks++) ldsm4(a[ks], arow + ks * 32);
#pragma unroll
        for (int nt = 0; nt < 16; nt += 2) {
            const uint32_t br0 = Bbs + (uint32_t)((nt * 8 + (lane & 7)) * QP + ((lane >> 3) & 3) * 16);
            const uint32_t br1 = br0 + 8 * QP;
            uint32_t b0[4], b1[4], d0[4], d1[4];
            ldsm4(b0, br0); ldsm4(b1, br0 + 64);
            ldsm4(d0, br1); ldsm4(d1, br1 + 64);
            mma16816(c[nt], a[0], b0);     mma16816(c[nt + 1], a[0], d0);
            mma16816(c[nt], a[1], b0 + 2); mma16816(c[nt + 1], a[1], d0 + 2);
            mma16816(c[nt], a[2], b1);     mma16816(c[nt + 1], a[2], d1);
            mma16816(c[nt], a[3], b1 + 2); mma16816(c[nt + 1], a[3], d1 + 2);
        }
    }
    __syncthreads();   // Q,K dead -> V may overwrite Q region

    // ---- V into smem (overwrites Q region); overlaps with softmax below ----
#pragma unroll
    for (int i = 0; i < 16; i++) {
        const int idx = i * 256 + t;
        const int row = idx >> 5, e2 = idx & 31;
        const uint32_t off = (uint32_t)(row * QP + e2 * 4);
        if (SPATIAL) {
            const uint2 w = *(const uint2*)(vpk + base + row * rstride + e2 * 2);
            *(uint32_t*)(sm + SV_H + off) = __byte_perm(w.x, w.y, 0x5410);
            *(uint32_t*)(sm + SV_L + off) = __byte_perm(w.x, w.y, 0x7632);
        } else {
            const float2 vv = *(const float2*)(v32 + base + row * rstride + e2 * 2);
            uint32_t hi, lo;
            split_pair(vv.x, vv.y, hi, lo);
            *(uint32_t*)(sm + SV_H + off) = hi;
            *(uint32_t*)(sm + SV_L + off) = lo;
        }
    }

    // ---- mask (spatial) + softmax (no max pass; logits are small) ----
    const int row_lo = r0 + (lane >> 2);
    const int row_hi = row_lo + 8;
    if (SPATIAL) {
        const float* mrow_lo = mask + ((size_t)b * Nn + row_lo) * Nn;
        const float* mrow_hi = mask + ((size_t)b * Nn + row_hi) * Nn;
#pragma unroll
        for (int nt = 0; nt < 16; nt++) {
            const int col = nt * 8 + (lane & 3) * 2;
            const float2 ml = *(const float2*)(mrow_lo + col);
            const float2 mh = *(const float2*)(mrow_hi + col);
            c[nt][0] *= ml.x; c[nt][1] *= ml.y;
            c[nt][2] *= mh.x; c[nt][3] *= mh.y;
        }
    }
    float slo = 0.f, shi = 0.f;
#pragma unroll
    for (int nt = 0; nt < 16; nt++) {
        c[nt][0] = exp2f(c[nt][0]);
        c[nt][1] = exp2f(c[nt][1]);
        c[nt][2] = exp2f(c[nt][2]);
        c[nt][3] = exp2f(c[nt][3]);
        slo += c[nt][0] + c[nt][1];
        shi += c[nt][2] + c[nt][3];
    }
    slo += __shfl_xor_sync(0xFFFFFFFF, slo, 1);
    slo += __shfl_xor_sync(0xFFFFFFFF, slo, 2);
    shi += __shfl_xor_sync(0xFFFFFFFF, shi, 1);
    shi += __shfl_xor_sync(0xFFFFFFFF, shi, 2);
    const float invlo = 1.0f / slo, invhi = 1.0f / shi;

    // ---- convert P to A-fragments in registers (C-frag == A-frag layout) ----
    uint32_t ph[32], pl[32];
#pragma unroll
    for (int kt = 0; kt < 8; kt++) {
        split_pair(c[2 * kt][0],     c[2 * kt][1],     ph[kt * 4 + 0], pl[kt * 4 + 0]);
        split_pair(c[2 * kt][2],     c[2 * kt][3],     ph[kt * 4 + 1], pl[kt * 4 + 1]);
        split_pair(c[2 * kt + 1][0], c[2 * kt + 1][1], ph[kt * 4 + 2], pl[kt * 4 + 2]);
        split_pair(c[2 * kt + 1][2], c[2 * kt + 1][3], ph[kt * 4 + 3], pl[kt * 4 + 3]);
    }
    __syncthreads();   // V tiles ready

    // ---- MMA2: O = Ph*Vh + Pl*Vh + Ph*Vl  (A in registers, B via ldsm4t) ----
    float o[8][4];
#pragma unroll
    for (int nt = 0; nt < 8; nt++)
#pragma unroll
        for (int j = 0; j < 4; j++) o[nt][j] = 0.f;

    const uint32_t vsel = (uint32_t)(((lane & 7) + ((lane >> 3) & 1) * 8) * QP
                                     + ((lane >> 4) & 1) * 16);
#pragma unroll
    for (int ks = 0; ks < 8; ks++) {
        const uint32_t* ah = ph + ks * 4;
        const uint32_t* al = pl + ks * 4;
        const uint32_t bh0 = sb + SV_H + (uint32_t)(ks * 16 * QP) + vsel;
        const uint32_t bl0 = sb + SV_L + (uint32_t)(ks * 16 * QP) + vsel;
#pragma unroll
        for (int p = 0; p < 4; p++) {
            uint32_t bb[4];
            ldsm4t(bb, bh0 + p * 32);
            mma16816(o[2 * p],     ah, bb);
            mma16816(o[2 * p + 1], ah, bb + 2);
            mma16816(o[2 * p],     al, bb);
            mma16816(o[2 * p + 1], al, bb + 2);
        }
#pragma unroll
        for (int p = 0; p < 4; p++) {
            uint32_t bb[4];
            ldsm4t(bb, bl0 + p * 32);
            mma16816(o[2 * p],     ah, bb);
            mma16816(o[2 * p + 1], ah, bb + 2);
        }
    }

    // ---- epilogue ----
    if (SPATIAL) {
        float* orow_lo = dst_f + base + row_lo * rstride;
        float* orow_hi = dst_f + base + row_hi * rstride;
#pragma unroll
        for (int nt = 0; nt < 8; nt++) {
            const int col = nt * 8 + (lane & 3) * 2;
            *(float2*)(orow_lo + col) = make_float2(o[nt][0] * invlo, o[nt][1] * invlo);
            *(float2*)(orow_hi + col) = make_float2(o[nt][2] * invhi, o[nt][3] * invhi);
        }
    } else {
        // pack each element as bf16 hi | lo<<16 for the spatial stage
        uint32_t* orow_lo = dst_pk + base + row_lo * rstride;
        uint32_t* orow_hi = dst_pk + base + row_hi * rstride;
#pragma unroll
        for (int nt = 0; nt < 8; nt++) {
            const int col = nt * 8 + (lane & 3) * 2;
            {
                const float f0 = o[nt][0] * invlo, f1 = o[nt][1] * invlo;
                const uint32_t u0 = __float_as_uint(f0), u1 = __float_as_uint(f1);
                const float l0 = f0 - __uint_as_float(u0 & 0xFFFF0000u);
                const float l1 = f1 - __uint_as_float(u1 & 0xFFFF0000u);
                const uint32_t lop = cvt_bf16x2(l1, l0);
                uint2 w;
                w.x = __byte_perm(u0, lop, 0x5432);
                w.y = __byte_perm(u1, lop, 0x7632);
                *(uint2*)(orow_lo + col) = w;
            }
            {
                const float f0 = o[nt][2] * invhi, f1 = o[nt][3] * invhi;
                const uint32_t u0 = __float_as_uint(f0), u1 = __float_as_uint(f1);
                const float l0 = f0 - __uint_as_float(u0 & 0xFFFF0000u);
                const float l1 = f1 - __uint_as_float(u1 & 0xFFFF0000u);
                const uint32_t lop = cvt_bf16x2(l1, l0);
                uint2 w;
                w.x = __byte_perm(u0, lop, 0x5432);
                w.y = __byte_perm(u1, lop, 0x7632);
                *(uint2*)(orow_hi + col) = w;
            }
        }
    }
}

// ---------------------------------------------------------------------------
extern "C" void kernel_launch(void* const* d_in, const int* in_sizes, int n_in,
                              void* d_out, int out_size)
{
    const float* q    = (const float*)d_in[0];
    const float* k    = (const float*)d_in[1];
    const float* v    = (const float*)d_in[2];
    const float* mask = (const float*)d_in[3];
    float* out = (float*)d_out;

    uint32_t* vt;
    cudaGetSymbolAddress((void**)&vt, g_vt);

    cudaFuncSetAttribute(attn_mma_kernel<false>,
                         cudaFuncAttributeMaxDynamicSharedMemorySize, SM_TOTAL);
    cudaFuncSetAttribute(attn_mma_kernel<true>,
                         cudaFuncAttributeMaxDynamicSharedMemorySize, SM_TOTAL);

    attn_mma_kernel<false><<<Bb * Nn * Hh, 256, SM_TOTAL>>>(
        q, k, v, nullptr, nullptr, vt, nullptr);
    attn_mma_kernel<true><<<Bb * Ll * Hh, 256, SM_TOTAL>>>(
        q, k, nullptr, (const uint32_t*)vt, mask, nullptr, out);
}